// round 10
// baseline (speedup 1.0000x reference)
#include <cuda_runtime.h>
#include <cstdint>

#define BATCH 2048
#define D0 256
#define D1 256
#define D2 256
#define D3 128

// Scratch (device globals: allocation-free per harness rules)
__device__ float g_We0[D1 * D0];
__device__ float g_We1[D2 * D1];
__device__ float g_We2[D3 * D2];
__device__ float g_h1[BATCH * D1];
__device__ float g_h2[BATCH * D2];

__device__ __forceinline__ float tanh_fast(float x) {
    float y;
    asm("tanh.approx.f32 %0, %1;" : "=f"(y) : "f"(x));
    return y;
}

__device__ __forceinline__ float atom_apply(float w, int idx) {
    float v = w;                       // identity
    if (idx == 1)      v = sinf(w);
    else if (idx == 2) v = tanhf(w);
    else if (idx == 3) v = w * w;
    return v;
}

// Precompute effective weights We = atom(W, idx) for all three layers.
__global__ void prep_we_kernel(const float* __restrict__ W0, const int* __restrict__ f0,
                               const float* __restrict__ W1, const int* __restrict__ f1,
                               const float* __restrict__ W2, const int* __restrict__ f2) {
    const int n01 = D1 * D0;           // 65536
    const int n2  = D3 * D2;           // 32768
    const int stride = gridDim.x * blockDim.x;
    for (int t = blockIdx.x * blockDim.x + threadIdx.x; t < n01; t += stride) {
        g_We0[t] = atom_apply(W0[t], f0[t]);
        g_We1[t] = atom_apply(W1[t], f1[t]);
    }
    for (int t = blockIdx.x * blockDim.x + threadIdx.x; t < n2; t += stride) {
        g_We2[t] = atom_apply(W2[t], f2[t]);
    }
}

// Hidden layer: h_out[b,o] = sum_i tanh(h[b,i]*We[o,i]) + bias[o]
// MUFU-bound (tanh.approx.f32, 16 elem/cyc/SM) — measured at floor; unchanged.
template <int IN>
__global__ __launch_bounds__(256) void layer_tanh_kernel(
    const float* __restrict__ h_in,   // [BATCH, IN]
    const float* __restrict__ We,     // [OUT, IN]
    const float* __restrict__ bias,   // [OUT]
    float* __restrict__ h_out,        // [BATCH, OUT]
    int OUT) {
    __shared__ float We_s[IN][33];    // [i][o_local]
    __shared__ float h_s[8][IN];

    const int tx = threadIdx.x;
    const int ty = threadIdx.y;
    const int tid = ty * 32 + tx;
    const int o0 = blockIdx.x * 32;
    const int b0 = blockIdx.y * 8;

    for (int idx = tid; idx < 32 * IN; idx += 256) {
        int o = idx / IN;
        int i = idx - o * IN;
        We_s[i][o] = We[(o0 + o) * IN + i];
    }
    const float4* Hg = reinterpret_cast<const float4*>(h_in + b0 * IN);
    float4* Hs = reinterpret_cast<float4*>(&h_s[0][0]);
    for (int idx = tid; idx < 8 * IN / 4; idx += 256) {
        Hs[idx] = Hg[idx];
    }
    __syncthreads();

    float acc0 = 0.f, acc1 = 0.f;
#pragma unroll 8
    for (int i = 0; i < IN; i += 2) {
        float z0 = h_s[ty][i]     * We_s[i][tx];
        float z1 = h_s[ty][i + 1] * We_s[i + 1][tx];
        acc0 += tanh_fast(z0);
        acc1 += tanh_fast(z1);
    }
    h_out[(b0 + ty) * OUT + o0 + tx] = acc0 + acc1 + bias[o0 + tx];
}

// Last layer (identity): fp32 GEMM. Tile 32o x 16b -> grid 512 (~3.5 CTAs/SM,
// 4 resident at 50KB smem). Thread: 1 output x 2 batches. KC = full 256 (one
// barrier). Per 4k: 1 LDS.128 W (stride-260 rows, conflict-free) + 2 LDS.128 h
// (warp-uniform broadcast) + 8 FFMA.
__global__ __launch_bounds__(256) void layer_lin_kernel(
    const float* __restrict__ h_in,     // [BATCH, 256]
    const float* __restrict__ We,       // [128, 256]
    const float* __restrict__ bias,     // [128]
    float* __restrict__ out) {          // [BATCH, 128]
    constexpr int IN = 256, OUT = D3;
    constexpr int RS = IN + 4;          // 260 floats: stride mod 32 = 4 -> LDS.128 conflict-free
    __shared__ float W_s[32 * RS];      // 33.3 KB
    __shared__ float h_s[16 * RS];      // 16.6 KB

    const int tx = threadIdx.x;         // 0..31 -> output
    const int ty = threadIdx.y;         // 0..7  -> batch pair
    const int tid = ty * 32 + tx;
    const int o0 = blockIdx.x * 32;
    const int b0 = blockIdx.y * 16;
    const int bl = ty * 2;

    // Stage W tile: 32 rows x 256 k (8 float4 per thread, gmem coalesced).
    for (int idx = tid; idx < 32 * (IN / 4); idx += 256) {
        int o = idx >> 6;               // /64
        int k4 = idx & 63;
        float4 v = *reinterpret_cast<const float4*>(&We[(o0 + o) * IN + k4 * 4]);
        *reinterpret_cast<float4*>(&W_s[o * RS + k4 * 4]) = v;
    }
    // Stage h tile: 16 rows x 256 k (4 float4 per thread).
    for (int idx = tid; idx < 16 * (IN / 4); idx += 256) {
        int b = idx >> 6;
        int k4 = idx & 63;
        float4 v = *reinterpret_cast<const float4*>(&h_in[(b0 + b) * IN + k4 * 4]);
        *reinterpret_cast<float4*>(&h_s[b * RS + k4 * 4]) = v;
    }
    __syncthreads();

    const float* wp  = &W_s[tx * RS];
    const float* hp0 = &h_s[bl * RS];
    const float* hp1 = &h_s[(bl + 1) * RS];
    float acc0 = 0.f, acc1 = 0.f, acc2 = 0.f, acc3 = 0.f;
#pragma unroll 16
    for (int k = 0; k < IN; k += 4) {
        float4 w  = *reinterpret_cast<const float4*>(wp + k);
        float4 h0 = *reinterpret_cast<const float4*>(hp0 + k);
        float4 h1 = *reinterpret_cast<const float4*>(hp1 + k);
        acc0 += w.x * h0.x + w.y * h0.y;
        acc1 += w.z * h0.z + w.w * h0.w;
        acc2 += w.x * h1.x + w.y * h1.y;
        acc3 += w.z * h1.z + w.w * h1.w;
    }

    float bb = bias[o0 + tx];
    out[(b0 + bl)     * OUT + o0 + tx] = acc0 + acc1 + bb;
    out[(b0 + bl + 1) * OUT + o0 + tx] = acc2 + acc3 + bb;
}

extern "C" void kernel_launch(void* const* d_in, const int* in_sizes, int n_in,
                              void* d_out, int out_size) {
    // Resolve input ordering at runtime (dict vs signature order).
    const float *x, *W0, *b0, *W1, *b1, *W2, *b2;
    const int *f0, *f1, *f2;
    x = (const float*)d_in[0];
    if (in_sizes[4] == 256) {
        // signature order: x, W0,b0, W1,b1, W2,b2, f0,f1,f2
        W0 = (const float*)d_in[1]; b0 = (const float*)d_in[2];
        W1 = (const float*)d_in[3]; b1 = (const float*)d_in[4];
        W2 = (const float*)d_in[5]; b2 = (const float*)d_in[6];
        f0 = (const int*)d_in[7];  f1 = (const int*)d_in[8];  f2 = (const int*)d_in[9];
    } else {
        // dict order: x, W0,b0,f0, W1,b1,f1, W2,b2,f2
        W0 = (const float*)d_in[1]; b0 = (const float*)d_in[2]; f0 = (const int*)d_in[3];
        W1 = (const float*)d_in[4]; b1 = (const float*)d_in[5]; f1 = (const int*)d_in[6];
        W2 = (const float*)d_in[7]; b2 = (const float*)d_in[8]; f2 = (const int*)d_in[9];
    }

    float *dWe0, *dWe1, *dWe2, *dh1, *dh2;
    cudaGetSymbolAddress((void**)&dWe0, g_We0);
    cudaGetSymbolAddress((void**)&dWe1, g_We1);
    cudaGetSymbolAddress((void**)&dWe2, g_We2);
    cudaGetSymbolAddress((void**)&dh1, g_h1);
    cudaGetSymbolAddress((void**)&dh2, g_h2);

    float* out = (float*)d_out;

    prep_we_kernel<<<256, 256>>>(W0, f0, W1, f1, W2, f2);

    dim3 blk(32, 8);
    // Layer 0: x[2048,256] -> h1[2048,256], tanh (MUFU f32)
    layer_tanh_kernel<D0><<<dim3(D1 / 32, BATCH / 8), blk>>>(x, dWe0, b0, dh1, D1);
    // Layer 1: h1 -> h2[2048,256], tanh (MUFU f32)
    layer_tanh_kernel<D1><<<dim3(D2 / 32, BATCH / 8), blk>>>(dh1, dWe1, b1, dh2, D2);
    // Layer 2: h2 -> out[2048,128], identity GEMM (32o x 16b tiles, 512 CTAs)
    layer_lin_kernel<<<dim3(D3 / 32, BATCH / 16), blk>>>(dh2, dWe2, b2, out);
}